// round 1
// baseline (speedup 1.0000x reference)
#include <cuda_runtime.h>
#include <cuda_bf16.h>

#define FULL 0xffffffffu

static constexpr int B = 64;
static constexpr int S = 512;
static constexpr int H = 768;
static constexpr int L = 9;

// Scratch (no allocations allowed): emissions + per-batch partials
__device__ float g_em[B * S * L];     // [b][t][j]
__device__ float g_score[B];
__device__ float g_logZ[B];
__device__ float g_corr[B];

// ---------------------------------------------------------------------------
// Kernel 1: emissions = hidden @ W + b    (HBM-bound, stream hidden once)
// block = 256 threads (8 warps), each warp computes 4 rows; grid = 1024
// ---------------------------------------------------------------------------
__global__ void emis_kernel(const float* __restrict__ hidden,
                            const float* __restrict__ W,
                            const float* __restrict__ bias) {
    __shared__ float sW[H * L];  // 27648 B
    for (int i = threadIdx.x; i < H * L; i += blockDim.x) sW[i] = W[i];
    __syncthreads();

    int warp = threadIdx.x >> 5;
    int lane = threadIdx.x & 31;
    int row0 = (blockIdx.x * 8 + warp) * 4;   // 4 rows per warp
    const float* h0 = hidden + (long)row0 * H;

    float acc[4][9];
#pragma unroll
    for (int r = 0; r < 4; r++)
#pragma unroll
        for (int j = 0; j < 9; j++) acc[r][j] = 0.f;

#pragma unroll 4
    for (int k = 0; k < H / 32; k++) {
        int h = k * 32 + lane;
        float w[9];
#pragma unroll
        for (int j = 0; j < 9; j++) w[j] = sW[h * 9 + j];  // 9h mod 32: conflict-free
#pragma unroll
        for (int r = 0; r < 4; r++) {
            float x = h0[(long)r * H + h];
#pragma unroll
            for (int j = 0; j < 9; j++) acc[r][j] = fmaf(x, w[j], acc[r][j]);
        }
    }

    // butterfly reduce each accumulator across the warp
#pragma unroll
    for (int r = 0; r < 4; r++)
#pragma unroll
        for (int j = 0; j < 9; j++) {
#pragma unroll
            for (int o = 16; o > 0; o >>= 1)
                acc[r][j] += __shfl_xor_sync(FULL, acc[r][j], o);
        }

    if (lane == 0) {
        float bb[9];
#pragma unroll
        for (int j = 0; j < 9; j++) bb[j] = bias[j];
#pragma unroll
        for (int r = 0; r < 4; r++) {
            float* dst = g_em + (long)(row0 + r) * 9;
#pragma unroll
            for (int j = 0; j < 9; j++) dst[j] = acc[r][j] + bb[j];
        }
    }
}

// ---------------------------------------------------------------------------
// Kernel 2: mega-kernel, 192 blocks x 32 threads
//   blocks   0.. 63 : forward DP (logZ)                [latency-bound]
//   blocks  64..127 : Viterbi forward + backtrace + predict + correct
//   blocks 128..191 : gold-path score (numerator) + label_flat copy
// ---------------------------------------------------------------------------
__global__ void crf_kernel(const int* __restrict__ label,
                           const int* __restrict__ mask,
                           const float* __restrict__ startT,
                           const float* __restrict__ endT,
                           const float* __restrict__ trans,
                           float* __restrict__ out) {
    __shared__ unsigned char bp[(S - 1) * L];  // Viterbi backpointers (4599 B)

    int blk = blockIdx.x;
    int lane = threadIdx.x;
    int jj = lane % 9;

    if (blk < 64) {
        // ------------------- forward algorithm (logZ) -------------------
        int b = blk;
        const float* emb = g_em + (long)b * S * L;
        const int* mb = mask + b * S;
        float Tc[9];
#pragma unroll
        for (int i = 0; i < 9; i++) Tc[i] = trans[i * 9 + jj];
        float alpha = startT[jj] + emb[jj];

        for (int t = 1; t < S; t++) {
            float e = emb[t * 9 + jj];
            int mt = mb[t];
            float ai[9];
#pragma unroll
            for (int i = 0; i < 9; i++)
                ai[i] = __shfl_sync(FULL, alpha, i) + Tc[i];
            float m = ai[0];
#pragma unroll
            for (int i = 1; i < 9; i++) m = fmaxf(m, ai[i]);
            float ssum = 0.f;
#pragma unroll
            for (int i = 0; i < 9; i++) ssum += __expf(ai[i] - m);
            float nxt = m + __logf(ssum) + e;
            alpha = (mt > 0) ? nxt : alpha;
        }
        float fin = alpha + endT[jj];
        float vi[9];
#pragma unroll
        for (int i = 0; i < 9; i++) vi[i] = __shfl_sync(FULL, fin, i);
        float m = vi[0];
#pragma unroll
        for (int i = 1; i < 9; i++) m = fmaxf(m, vi[i]);
        float ssum = 0.f;
#pragma unroll
        for (int i = 0; i < 9; i++) ssum += __expf(vi[i] - m);
        if (lane == 0) g_logZ[b] = m + __logf(ssum);

    } else if (blk < 128) {
        // ------------------- Viterbi decode -------------------
        int b = blk - 64;
        const float* emb = g_em + (long)b * S * L;
        float Tc[9];
#pragma unroll
        for (int i = 0; i < 9; i++) Tc[i] = trans[i * 9 + jj];
        float v = startT[jj] + emb[jj];

        for (int t = 1; t < S; t++) {
            float e = emb[t * 9 + jj];
            float vi[9];
#pragma unroll
            for (int i = 0; i < 9; i++)
                vi[i] = (__shfl_sync(FULL, v, i) + Tc[i]) + e;  // ref op order
            float best = vi[0];
            int arg = 0;
#pragma unroll
            for (int i = 1; i < 9; i++)
                if (vi[i] > best) { best = vi[i]; arg = i; }    // first-max tie
            v = best;
            if (lane < 9) bp[(t - 1) * 9 + jj] = (unsigned char)arg;
        }
        __syncwarp();

        float fj = v + endT[jj];
        float fv[9];
#pragma unroll
        for (int i = 0; i < 9; i++) fv[i] = __shfl_sync(FULL, fj, i);

        if (lane == 0) {
            float best = fv[0];
            int tag = 0;
#pragma unroll
            for (int i = 1; i < 9; i++)
                if (fv[i] > best) { best = fv[i]; tag = i; }
            const int* lb = label + b * S;
            float* pout = out + 2 + (long)b * S;
            float cnt = 0.f;
            {
                int lab = lb[S - 1];
                int pv = (lab > 0) ? tag : 0;
                pout[S - 1] = (float)pv;
                cnt += (pv == lab) ? 1.f : 0.f;
            }
            for (int t = S - 2; t >= 0; t--) {
                tag = bp[t * 9 + tag];
                int lab = lb[t];
                int pv = (lab > 0) ? tag : 0;
                pout[t] = (float)pv;
                cnt += (pv == lab) ? 1.f : 0.f;
            }
            g_corr[b] = cnt;
        }

    } else {
        // --------------- gold path score (masked scan) + label copy ---------------
        int b = blk - 128;
        const int* lb = label + b * S;
        const int* mb = mask + b * S;
        const float* emb = g_em + (long)b * S * L;
        int t0 = lane * 16;

        // pass 1: local last-flagged index (flag: t==0 or mask>0)
        int ll = -1;
#pragma unroll
        for (int k = 0; k < 16; k++) {
            int t = t0 + k;
            if ((t == 0) | (mb[t] > 0)) ll = t;
        }
        int inc = ll;
#pragma unroll
        for (int o = 1; o < 32; o <<= 1) {
            int vv = __shfl_up_sync(FULL, inc, o);
            if (lane >= o) inc = max(inc, vv);
        }
        int exc = __shfl_up_sync(FULL, inc, 1);
        if (lane == 0) exc = -1;
        int lastAll = __shfl_sync(FULL, inc, 31);

        // pass 2: accumulate masked transition+emission terms
        float sc = 0.f;
        int prevIdx = exc;
#pragma unroll
        for (int k = 0; k < 16; k++) {
            int t = t0 + k;
            int mt = mb[t];
            int tg = lb[t];
            if (t >= 1) {
                int pt = lb[prevIdx];
                float s = trans[pt * 9 + tg] + emb[t * 9 + tg];
                sc += s * (float)mt;
            }
            if ((t == 0) | (mt > 0)) prevIdx = t;
        }
#pragma unroll
        for (int o = 16; o > 0; o >>= 1) sc += __shfl_xor_sync(FULL, sc, o);

        if (lane == 0) {
            int tg0 = lb[0];
            g_score[b] = startT[tg0] + emb[tg0] + sc + endT[lb[lastAll]];
        }

        // label_flat copy (float cast)
        float* lout = out + 2 + (long)B * S;
        for (int t = lane; t < S; t += 32)
            lout[(long)b * S + t] = (float)lb[t];
    }
}

// ---------------------------------------------------------------------------
// Kernel 3: finalize loss & correct
// ---------------------------------------------------------------------------
__global__ void fin_kernel(float* __restrict__ out) {
    __shared__ float sd[64], sc[64];
    int i = threadIdx.x;
    sd[i] = g_score[i] - g_logZ[i];
    sc[i] = g_corr[i];
    __syncthreads();
    if (i == 0) {
        float s = 0.f, c = 0.f;
        for (int k = 0; k < 64; k++) { s += sd[k]; c += sc[k]; }
        out[0] = -s / (float)B;
        out[1] = c;
    }
}

// ---------------------------------------------------------------------------
extern "C" void kernel_launch(void* const* d_in, const int* in_sizes, int n_in,
                              void* d_out, int out_size) {
    const float* hidden = (const float*)d_in[0];
    const int*   label  = (const int*)d_in[1];
    const int*   mask   = (const int*)d_in[2];
    const float* W      = (const float*)d_in[3];
    const float* bias   = (const float*)d_in[4];
    const float* startT = (const float*)d_in[5];
    const float* endT   = (const float*)d_in[6];
    const float* trans  = (const float*)d_in[7];
    float* out = (float*)d_out;

    emis_kernel<<<1024, 256>>>(hidden, W, bias);
    crf_kernel<<<192, 32>>>(label, mask, startT, endT, trans, out);
    fin_kernel<<<1, 64>>>(out);
}